// round 1
// baseline (speedup 1.0000x reference)
#include <cuda_runtime.h>
#include <math.h>

// Problem constants
#define N_B    8
#define SEQ    512
#define DMODEL 4096
#define HEADS  8
#define HDIM   512
#define MTOT   (N_B * SEQ)      // 4096 (flattened rows for projections)
#define NBATCH (N_B * HEADS)    // 64  (batched scores GEMM)

// Scratch (allocation-free rule: __device__ globals)
__device__ float g_Q[MTOT * DMODEL];
__device__ float g_K[MTOT * DMODEL];
__device__ float g_V[MTOT * DMODEL];
__device__ float g_S[NBATCH * SEQ * SEQ];
__device__ float g_Y[MTOT * DMODEL];

// ----------------------------------------------------------------------------
// NT SGEMM: C[m][n] = scale * sum_k A[m][k]*B[n][k] + bias[n]
// A: M x K row-major, B: N x K row-major (i.e. C = A * B^T), batched via z.
// 128x128 block tile, BK=8, 256 threads, 8x8 per-thread microtile.
// All dims here are multiples of the tile sizes -> no bounds checks.
// ----------------------------------------------------------------------------
__global__ void __launch_bounds__(256) sgemm_nt(
    const float* __restrict__ A, const float* __restrict__ B,
    float* __restrict__ C, const float* __restrict__ bias,
    float scale, int M, int Nn, int K,
    long long sA, long long sB, long long sC)
{
    A += (long long)blockIdx.z * sA;
    B += (long long)blockIdx.z * sB;
    C += (long long)blockIdx.z * sC;

    __shared__ float As[8][132];   // k-major, padded to dodge store conflicts
    __shared__ float Bs[8][132];

    const int tid = threadIdx.x;
    const int bm  = blockIdx.y * 128;
    const int bn  = blockIdx.x * 128;

    // loader: 256 threads x one float4 = 128x8 tile
    const int lrow = tid >> 1;           // 0..127
    const int lcol = (tid & 1) * 4;      // 0 or 4

    // compute mapping: 16x16 thread grid, 8x8 microtile
    const int ty = (tid >> 4) * 8;       // 0..120
    const int tx = (tid & 15) * 8;       // 0..120

    float acc[8][8];
    #pragma unroll
    for (int i = 0; i < 8; i++)
        #pragma unroll
        for (int j = 0; j < 8; j++)
            acc[i][j] = 0.f;

    for (int k0 = 0; k0 < K; k0 += 8) {
        float4 a4 = *reinterpret_cast<const float4*>(
            A + (long long)(bm + lrow) * K + (k0 + lcol));
        float4 b4 = *reinterpret_cast<const float4*>(
            B + (long long)(bn + lrow) * K + (k0 + lcol));
        As[lcol + 0][lrow] = a4.x;
        As[lcol + 1][lrow] = a4.y;
        As[lcol + 2][lrow] = a4.z;
        As[lcol + 3][lrow] = a4.w;
        Bs[lcol + 0][lrow] = b4.x;
        Bs[lcol + 1][lrow] = b4.y;
        Bs[lcol + 2][lrow] = b4.z;
        Bs[lcol + 3][lrow] = b4.w;
        __syncthreads();

        #pragma unroll
        for (int k = 0; k < 8; k++) {
            float4 a0 = *reinterpret_cast<const float4*>(&As[k][ty]);
            float4 a1 = *reinterpret_cast<const float4*>(&As[k][ty + 4]);
            float4 b0 = *reinterpret_cast<const float4*>(&Bs[k][tx]);
            float4 b1 = *reinterpret_cast<const float4*>(&Bs[k][tx + 4]);
            float ra[8] = {a0.x, a0.y, a0.z, a0.w, a1.x, a1.y, a1.z, a1.w};
            float rb[8] = {b0.x, b0.y, b0.z, b0.w, b1.x, b1.y, b1.z, b1.w};
            #pragma unroll
            for (int i = 0; i < 8; i++)
                #pragma unroll
                for (int j = 0; j < 8; j++)
                    acc[i][j] = fmaf(ra[i], rb[j], acc[i][j]);
        }
        __syncthreads();
    }

    #pragma unroll
    for (int i = 0; i < 8; i++) {
        long long row = (long long)(bm + ty + i);
        #pragma unroll
        for (int j = 0; j < 8; j += 4) {
            int col = bn + tx + j;
            float4 o;
            o.x = acc[i][j + 0] * scale;
            o.y = acc[i][j + 1] * scale;
            o.z = acc[i][j + 2] * scale;
            o.w = acc[i][j + 3] * scale;
            if (bias) {
                o.x += bias[col + 0];
                o.y += bias[col + 1];
                o.z += bias[col + 2];
                o.w += bias[col + 3];
            }
            *reinterpret_cast<float4*>(C + row * Nn + col) = o;
        }
    }
}

// ----------------------------------------------------------------------------
// Column softmax (over s) + elementwise multiply by V + head-interleave scatter.
// One thread per (batch b = n*H+h, column t). Online max/sum pass, then write
//   Y[n, s, h*HDIM + t] = softmax_s(S[b,s,t]) * V[b,s,t]
// ----------------------------------------------------------------------------
__global__ void __launch_bounds__(256) softmax_mul_scatter(
    const float* __restrict__ S, const float* __restrict__ V,
    float* __restrict__ Y)
{
    int idx = blockIdx.x * blockDim.x + threadIdx.x;   // 0 .. 64*512-1
    int b = idx >> 9;
    int t = idx & 511;
    int n = b >> 3;
    int h = b & 7;

    const float* col  = S + (long long)b * SEQ * SEQ + t;
    const float* vcol = V + (long long)b * SEQ * SEQ + t;
    float* ycol = Y + (long long)n * SEQ * DMODEL + h * HDIM + t;

    float m = -1e30f, l = 0.f;
    for (int s = 0; s < SEQ; s++) {
        float x = col[(long long)s * SEQ];
        float nm = fmaxf(m, x);
        l = l * __expf(m - nm) + __expf(x - nm);
        m = nm;
    }
    float inv = 1.f / l;
    for (int s = 0; s < SEQ; s++) {
        float x = col[(long long)s * SEQ];
        ycol[(long long)s * DMODEL] = __expf(x - m) * inv * vcol[(long long)s * SEQ];
    }
}

// ----------------------------------------------------------------------------
extern "C" void kernel_launch(void* const* d_in, const int* in_sizes, int n_in,
                              void* d_out, int out_size)
{
    const float* query = (const float*)d_in[0];
    const float* key   = (const float*)d_in[1];
    const float* value = (const float*)d_in[2];
    const float* Wq    = (const float*)d_in[3];
    const float* bq    = (const float*)d_in[4];
    const float* Wk    = (const float*)d_in[5];
    const float* bk    = (const float*)d_in[6];
    const float* Wv    = (const float*)d_in[7];
    const float* bv    = (const float*)d_in[8];
    const float* Wo    = (const float*)d_in[9];
    const float* bo    = (const float*)d_in[10];
    float* out = (float*)d_out;

    float *Q, *K, *V, *Sc, *Y;
    cudaGetSymbolAddress((void**)&Q,  g_Q);
    cudaGetSymbolAddress((void**)&K,  g_K);
    cudaGetSymbolAddress((void**)&V,  g_V);
    cudaGetSymbolAddress((void**)&Sc, g_S);
    cudaGetSymbolAddress((void**)&Y,  g_Y);

    dim3 blk(256);
    dim3 gBig(DMODEL / 128, MTOT / 128, 1);          // 32 x 32

    // 1-3) Projections: P = X @ W^T + b   (M=4096, N=4096, K=4096)
    sgemm_nt<<<gBig, blk>>>(query, Wq, Q, bq, 1.f, MTOT, DMODEL, DMODEL, 0, 0, 0);
    sgemm_nt<<<gBig, blk>>>(key,   Wk, K, bk, 1.f, MTOT, DMODEL, DMODEL, 0, 0, 0);
    sgemm_nt<<<gBig, blk>>>(value, Wv, V, bv, 1.f, MTOT, DMODEL, DMODEL, 0, 0, 0);

    // 4) scores[b] = (1/sqrt(512)) * Q_b @ K_b^T, b = 0..63, each 512x512x512
    {
        dim3 gSc(SEQ / 128, SEQ / 128, NBATCH);      // 4 x 4 x 64
        float scale = rsqrtf((float)HDIM);
        long long sb = (long long)SEQ * SEQ;         // == SEQ*HDIM for Q/K view
        sgemm_nt<<<gSc, blk>>>(Q, K, Sc, nullptr, scale, SEQ, SEQ, HDIM, sb, sb, sb);
    }

    // 5) column softmax (axis=s) * V, scattered into (N, S, D) layout
    softmax_mul_scatter<<<(NBATCH * SEQ) / 256, blk>>>(Sc, V, Y);

    // 6) out = Y @ Wo^T + bo
    sgemm_nt<<<gBig, blk>>>(Y, Wo, out, bo, 1.f, MTOT, DMODEL, DMODEL, 0, 0, 0);
}

// round 5
// speedup vs baseline: 5.2173x; 5.2173x over previous
#include <cuda_runtime.h>
#include <cuda_bf16.h>
#include <stdint.h>
#include <math.h>

typedef __nv_bfloat16 bf16;

#define N_B    8
#define SEQ    512
#define DMODEL 4096
#define HEADS  8
#define HDIM   512
#define MTOT   4096
#define NBATCH 64
#define NELEM  (MTOT * DMODEL)

// GEMM tiling (mma.sync path, baseline PTX only)
#define BM   128
#define BN   128
#define BK   64                       // K per stage (128B rows)
#define STG  3
#define GT   256                      // 8 warps
#define A_BYTES (BM * 128)            // 16 KB
#define B_BYTES (BN * 128)            // 16 KB
#define STAGE_BYTES (A_BYTES + B_BYTES)
#define SMEM_REQ (STG * STAGE_BYTES)  // 96 KB

// ---------------------------------------------------------------------------
// Scratch (__device__ globals; allocation-free rule)
// ---------------------------------------------------------------------------
__device__ bf16 g_Xq_h[NELEM], g_Xq_l[NELEM];
__device__ bf16 g_Xk_h[NELEM], g_Xk_l[NELEM];
__device__ bf16 g_Xv_h[NELEM], g_Xv_l[NELEM];
__device__ bf16 g_Wq_h[NELEM], g_Wq_l[NELEM];
__device__ bf16 g_Wk_h[NELEM], g_Wk_l[NELEM];
__device__ bf16 g_Wv_h[NELEM], g_Wv_l[NELEM];
__device__ bf16 g_Wo_h[NELEM], g_Wo_l[NELEM];
__device__ bf16 g_Qh[NELEM], g_Ql[NELEM];
__device__ bf16 g_Kh[NELEM], g_Kl[NELEM];
__device__ bf16 g_Yh[NELEM], g_Yl[NELEM];
__device__ float g_V[NELEM];
__device__ float g_S[NELEM];

// ---------------------------------------------------------------------------
__device__ __forceinline__ uint32_t smem_u32(const void* p) {
    uint32_t a;
    asm("{ .reg .u64 t; cvta.to.shared.u64 t, %1; cvt.u32.u64 %0, t; }"
        : "=r"(a) : "l"(p));
    return a;
}
__device__ __forceinline__ void cp16(uint32_t dst, const void* src) {
    asm volatile("cp.async.cg.shared.global [%0], [%1], 16;"
                 :: "r"(dst), "l"(src) : "memory");
}
#define CP_COMMIT() asm volatile("cp.async.commit_group;" ::: "memory")
#define CP_WAIT(n)  asm volatile("cp.async.wait_group %0;" :: "n"(n) : "memory")

__device__ __forceinline__ void ldsm4(uint32_t& r0, uint32_t& r1,
                                      uint32_t& r2, uint32_t& r3, uint32_t a) {
    asm volatile("ldmatrix.sync.aligned.m8n8.x4.shared.b16 {%0,%1,%2,%3}, [%4];"
                 : "=r"(r0), "=r"(r1), "=r"(r2), "=r"(r3) : "r"(a));
}
__device__ __forceinline__ void mma16816(float* c, const uint32_t* a,
                                         const uint32_t* b) {
    asm volatile(
        "mma.sync.aligned.m16n8k16.row.col.f32.bf16.bf16.f32 "
        "{%0,%1,%2,%3}, {%4,%5,%6,%7}, {%8,%9}, {%0,%1,%2,%3};"
        : "+f"(c[0]), "+f"(c[1]), "+f"(c[2]), "+f"(c[3])
        : "r"(a[0]), "r"(a[1]), "r"(a[2]), "r"(a[3]), "r"(b[0]), "r"(b[1]));
}

// ---------------------------------------------------------------------------
// bf16x3 NT GEMM on mma.sync: C = scale*(Ah+Al)(Bh+Bl)^T + bias (Al*Bl dropped)
// A: M x Kp row-major, B: Nn x Kp row-major, batched via blockIdx.z.
// ---------------------------------------------------------------------------
__global__ void __launch_bounds__(GT)
gemm_bf16x3(const bf16* __restrict__ Ah, const bf16* __restrict__ Al,
            const bf16* __restrict__ Bh, const bf16* __restrict__ Bl,
            float* __restrict__ Cf, bf16* __restrict__ Chi, bf16* __restrict__ Clo,
            const float* __restrict__ bias, float scale,
            int Kp, int Nn, int spp,
            long long sA, long long sB, long long sC)
{
    extern __shared__ char smem[];
    const uint32_t SB = smem_u32(smem);

    const int tid  = threadIdx.x;
    const int lane = tid & 31;
    const int wid  = tid >> 5;
    const int wm   = wid >> 2;            // 0..1  -> 64-row slab
    const int wn   = wid & 3;             // 0..3  -> 32-col slab
    const long long z = blockIdx.z;
    const bf16* Ah_ = Ah + z * sA;
    const bf16* Al_ = Al + z * sA;
    const bf16* Bh_ = Bh + z * sB;
    const bf16* Bl_ = Bl + z * sB;
    const int bm = blockIdx.y * BM;
    const int bn = blockIdx.x * BN;
    const int NS = spp * 3;

    // ---- per-lane ldmatrix address bases (within a stage slot) ----
    const int grp = lane >> 3, lr = lane & 7;
    // A: tile mt (m16): rows = wm*64 + mt*16 + lr + (grp&1)*8, chunk base grp>>1
    uint32_t a_rowoff[4];
    uint32_t a_x7[4];
    #pragma unroll
    for (int mt = 0; mt < 4; mt++) {
        int r = wm * 64 + mt * 16 + lr + (grp & 1) * 8;
        a_rowoff[mt] = (uint32_t)r * 128;
        a_x7[mt] = (uint32_t)(r & 7);
    }
    const uint32_t a_cb = (uint32_t)(grp >> 1);
    // B: half h (16 n-rows): rows = wn*32 + h*16 + lr + (grp>=2)*8, chunk base grp&1
    uint32_t b_rowoff[2];
    uint32_t b_x7[2];
    #pragma unroll
    for (int h = 0; h < 2; h++) {
        int r = wn * 32 + h * 16 + lr + ((grp >> 1) & 1) * 8;
        b_rowoff[h] = (uint32_t)r * 128;
        b_x7[h] = (uint32_t)(r & 7);
    }
    const uint32_t b_cb = (uint32_t)(grp & 1);

    float acc[4][4][4];
    #pragma unroll
    for (int i = 0; i < 4; i++)
        #pragma unroll
        for (int j = 0; j < 4; j++)
            #pragma unroll
            for (int k = 0; k < 4; k++) acc[i][j][k] = 0.f;

    auto load_stage = [&](int slot, int ksv) {
        const int pass = ksv / spp;
        const int kk   = (ksv - pass * spp) * BK;
        const bf16* Ap = (pass == 2) ? Al_ : Ah_;
        const bf16* Bp = (pass == 1) ? Bl_ : Bh_;
        const uint32_t ab = SB + slot * STAGE_BYTES;
        const uint32_t bb = ab + A_BYTES;
        #pragma unroll
        for (int i = 0; i < 4; i++) {             // A: 1024 16B chunks
            int id = tid + i * GT, r = id >> 3, c = id & 7;
            cp16(ab + r * 128 + ((c ^ (r & 7)) * 16),
                 (const char*)(Ap + (size_t)(bm + r) * Kp + kk) + c * 16);
        }
        #pragma unroll
        for (int i = 0; i < 4; i++) {             // B: 1024 16B chunks
            int id = tid + i * GT, r = id >> 3, c = id & 7;
            cp16(bb + r * 128 + ((c ^ (r & 7)) * 16),
                 (const char*)(Bp + (size_t)(bn + r) * Kp + kk) + c * 16);
        }
    };

    #pragma unroll
    for (int s = 0; s < STG - 1; s++) { load_stage(s, s); CP_COMMIT(); }

    for (int ks = 0; ks < NS; ks++) {
        CP_WAIT(STG - 2);
        __syncthreads();

        const int kn = ks + STG - 1;
        if (kn < NS) load_stage(kn % STG, kn);
        CP_COMMIT();

        const uint32_t ab = SB + (ks % STG) * STAGE_BYTES;
        const uint32_t bb = ab + A_BYTES;

        #pragma unroll
        for (int kst = 0; kst < 4; kst++) {       // 4 x k16 per BK=64 stage
            uint32_t af[4][4], bf[2][4];
            #pragma unroll
            for (int mt = 0; mt < 4; mt++)
                ldsm4(af[mt][0], af[mt][1], af[mt][2], af[mt][3],
                      ab + a_rowoff[mt] + (((kst * 2 + a_cb) ^ a_x7[mt]) * 16));
            #pragma unroll
            for (int h = 0; h < 2; h++)
                ldsm4(bf[h][0], bf[h][1], bf[h][2], bf[h][3],
                      bb + b_rowoff[h] + (((kst * 2 + b_cb) ^ b_x7[h]) * 16));
            #pragma unroll
            for (int mt = 0; mt < 4; mt++)
                #pragma unroll
                for (int nt = 0; nt < 4; nt++)
                    mma16816(acc[mt][nt], af[mt], &bf[nt >> 1][(nt & 1) * 2]);
        }
    }

    // ------------------------- epilogue -------------------------
    const int qr = lane >> 2, qc = (lane & 3) * 2;
    #pragma unroll
    for (int mt = 0; mt < 4; mt++) {
        #pragma unroll
        for (int half = 0; half < 2; half++) {    // c0c1 then c2c3 (row+8)
            const size_t row = (size_t)(bm + wm * 64 + mt * 16 + qr + half * 8);
            #pragma unroll
            for (int nt = 0; nt < 4; nt++) {
                const int col = bn + wn * 32 + nt * 8 + qc;
                float v0 = acc[mt][nt][half * 2 + 0] * scale;
                float v1 = acc[mt][nt][half * 2 + 1] * scale;
                if (bias) { v0 += bias[col]; v1 += bias[col + 1]; }
                if (Cf) {
                    float2 o; o.x = v0; o.y = v1;
                    *reinterpret_cast<float2*>(Cf + z * sC + row * Nn + col) = o;
                } else {
                    bf16 h0 = __float2bfloat16(v0);
                    bf16 h1 = __float2bfloat16(v1);
                    __nv_bfloat162 hh; hh.x = h0; hh.y = h1;
                    __nv_bfloat162 ll;
                    ll.x = __float2bfloat16(v0 - __bfloat162float(h0));
                    ll.y = __float2bfloat16(v1 - __bfloat162float(h1));
                    *reinterpret_cast<__nv_bfloat162*>(Chi + z * sC + row * Nn + col) = hh;
                    *reinterpret_cast<__nv_bfloat162*>(Clo + z * sC + row * Nn + col) = ll;
                }
            }
        }
    }
}

// ---------------------------------------------------------------------------
// fp32 -> bf16 hi/lo split (elementwise)
// ---------------------------------------------------------------------------
__global__ void __launch_bounds__(256) split_f32(
    const float4* __restrict__ x, __nv_bfloat162* __restrict__ hi,
    __nv_bfloat162* __restrict__ lo, int n4)
{
    int i = blockIdx.x * 256 + threadIdx.x;
    if (i >= n4) return;
    float4 v = x[i];
    bf16 h0 = __float2bfloat16(v.x), h1 = __float2bfloat16(v.y);
    bf16 h2 = __float2bfloat16(v.z), h3 = __float2bfloat16(v.w);
    __nv_bfloat162 ha; ha.x = h0; ha.y = h1;
    __nv_bfloat162 hb; hb.x = h2; hb.y = h3;
    __nv_bfloat162 la, lb;
    la.x = __float2bfloat16(v.x - __bfloat162float(h0));
    la.y = __float2bfloat16(v.y - __bfloat162float(h1));
    lb.x = __float2bfloat16(v.z - __bfloat162float(h2));
    lb.y = __float2bfloat16(v.w - __bfloat162float(h3));
    hi[2 * i] = ha; hi[2 * i + 1] = hb;
    lo[2 * i] = la; lo[2 * i + 1] = lb;
}

// ---------------------------------------------------------------------------
// Column softmax (axis s) * V, head-interleave scatter, bf16 hi/lo split out
// ---------------------------------------------------------------------------
__global__ void __launch_bounds__(256) softmax_mul_scatter(
    const float* __restrict__ S, const float* __restrict__ V,
    bf16* __restrict__ Yh, bf16* __restrict__ Yl)
{
    int idx = blockIdx.x * blockDim.x + threadIdx.x;   // 0 .. 64*512-1
    int b = idx >> 9, t = idx & 511;
    int n = b >> 3, h = b & 7;

    const float* col  = S + (size_t)b * SEQ * SEQ + t;
    const float* vcol = V + (size_t)b * SEQ * SEQ + t;
    size_t ybase = (size_t)n * SEQ * DMODEL + h * HDIM + t;

    float m = -1e30f, l = 0.f;
    for (int s = 0; s < SEQ; s++) {
        float x = col[(size_t)s * SEQ];
        float nm = fmaxf(m, x);
        l = l * __expf(m - nm) + __expf(x - nm);
        m = nm;
    }
    float inv = 1.f / l;
    for (int s = 0; s < SEQ; s++) {
        float x  = col[(size_t)s * SEQ];
        float yv = __expf(x - m) * inv * vcol[(size_t)s * SEQ];
        bf16 hh = __float2bfloat16(yv);
        size_t off = ybase + (size_t)s * DMODEL;
        Yh[off] = hh;
        Yl[off] = __float2bfloat16(yv - __bfloat162float(hh));
    }
}

// ---------------------------------------------------------------------------
extern "C" void kernel_launch(void* const* d_in, const int* in_sizes, int n_in,
                              void* d_out, int out_size)
{
    const float* query = (const float*)d_in[0];
    const float* key   = (const float*)d_in[1];
    const float* value = (const float*)d_in[2];
    const float* Wq    = (const float*)d_in[3];
    const float* bq    = (const float*)d_in[4];
    const float* Wk    = (const float*)d_in[5];
    const float* bk    = (const float*)d_in[6];
    const float* Wv    = (const float*)d_in[7];
    const float* bv    = (const float*)d_in[8];
    const float* Wo    = (const float*)d_in[9];
    const float* bo    = (const float*)d_in[10];
    float* out = (float*)d_out;

    cudaFuncSetAttribute(gemm_bf16x3,
                         cudaFuncAttributeMaxDynamicSharedMemorySize, SMEM_REQ);

    bf16 *Xq_h, *Xq_l, *Xk_h, *Xk_l, *Xv_h, *Xv_l;
    bf16 *Wq_h, *Wq_l, *Wk_h, *Wk_l, *Wv_h, *Wv_l, *Wo_h, *Wo_l;
    bf16 *Qh, *Ql, *Kh, *Kl, *Yh, *Yl;
    float *Vf, *Sf;
    cudaGetSymbolAddress((void**)&Xq_h, g_Xq_h); cudaGetSymbolAddress((void**)&Xq_l, g_Xq_l);
    cudaGetSymbolAddress((void**)&Xk_h, g_Xk_h); cudaGetSymbolAddress((void**)&Xk_l, g_Xk_l);
    cudaGetSymbolAddress((void**)&Xv_h, g_Xv_h); cudaGetSymbolAddress((void**)&Xv_l, g_Xv_l);
    cudaGetSymbolAddress((void**)&Wq_h, g_Wq_h); cudaGetSymbolAddress((void**)&Wq_l, g_Wq_l);
    cudaGetSymbolAddress((void**)&Wk_h, g_Wk_h); cudaGetSymbolAddress((void**)&Wk_l, g_Wk_l);
    cudaGetSymbolAddress((void**)&Wv_h, g_Wv_h); cudaGetSymbolAddress((void**)&Wv_l, g_Wv_l);
    cudaGetSymbolAddress((void**)&Wo_h, g_Wo_h); cudaGetSymbolAddress((void**)&Wo_l, g_Wo_l);
    cudaGetSymbolAddress((void**)&Qh, g_Qh); cudaGetSymbolAddress((void**)&Ql, g_Ql);
    cudaGetSymbolAddress((void**)&Kh, g_Kh); cudaGetSymbolAddress((void**)&Kl, g_Kl);
    cudaGetSymbolAddress((void**)&Yh, g_Yh); cudaGetSymbolAddress((void**)&Yl, g_Yl);
    cudaGetSymbolAddress((void**)&Vf, g_V);  cudaGetSymbolAddress((void**)&Sf, g_S);

    const int n4 = NELEM / 4;
    const int sg = (n4 + 255) / 256;
    split_f32<<<sg, 256>>>((const float4*)query, (__nv_bfloat162*)Xq_h, (__nv_bfloat162*)Xq_l, n4);
    split_f32<<<sg, 256>>>((const float4*)key,   (__nv_bfloat162*)Xk_h, (__nv_bfloat162*)Xk_l, n4);
    split_f32<<<sg, 256>>>((const float4*)value, (__nv_bfloat162*)Xv_h, (__nv_bfloat162*)Xv_l, n4);
    split_f32<<<sg, 256>>>((const float4*)Wq,    (__nv_bfloat162*)Wq_h, (__nv_bfloat162*)Wq_l, n4);
    split_f32<<<sg, 256>>>((const float4*)Wk,    (__nv_bfloat162*)Wk_h, (__nv_bfloat162*)Wk_l, n4);
    split_f32<<<sg, 256>>>((const float4*)Wv,    (__nv_bfloat162*)Wv_h, (__nv_bfloat162*)Wv_l, n4);
    split_f32<<<sg, 256>>>((const float4*)Wo,    (__nv_bfloat162*)Wo_h, (__nv_bfloat162*)Wo_l, n4);

    dim3 blk(GT);
    dim3 gP(DMODEL / BN, MTOT / BM, 1);            // 32 x 32

    gemm_bf16x3<<<gP, blk, SMEM_REQ>>>(Xq_h, Xq_l, Wq_h, Wq_l,
        nullptr, Qh, Ql, bq, 1.f, DMODEL, DMODEL, DMODEL / BK, 0, 0, 0);
    gemm_bf16x3<<<gP, blk, SMEM_REQ>>>(Xk_h, Xk_l, Wk_h, Wk_l,
        nullptr, Kh, Kl, bk, 1.f, DMODEL, DMODEL, DMODEL / BK, 0, 0, 0);
    gemm_bf16x3<<<gP, blk, SMEM_REQ>>>(Xv_h, Xv_l, Wv_h, Wv_l,
        Vf, nullptr, nullptr, bv, 1.f, DMODEL, DMODEL, DMODEL / BK, 0, 0, 0);

    {   // scores: 64 x (512x512x512)
        dim3 gS(SEQ / BN, SEQ / BM, NBATCH);       // 4 x 4 x 64
        long long sbz = (long long)SEQ * SEQ;
        gemm_bf16x3<<<gS, blk, SMEM_REQ>>>(Qh, Ql, Kh, Kl,
            Sf, nullptr, nullptr, nullptr, rsqrtf((float)HDIM),
            HDIM, SEQ, HDIM / BK, sbz, sbz, sbz);
    }

    softmax_mul_scatter<<<(NBATCH * SEQ) / 256, 256>>>(Sf, Vf, Yh, Yl);

    gemm_bf16x3<<<gP, blk, SMEM_REQ>>>(Yh, Yl, Wo_h, Wo_l,
        out, nullptr, nullptr, bo, 1.f, DMODEL, DMODEL, DMODEL / BK, 0, 0, 0);
}